// round 10
// baseline (speedup 1.0000x reference)
#include <cuda_runtime.h>
#include <cuda_fp16.h>
#include <cuda_bf16.h>
#include <math.h>
#include <stdint.h>
#include <string.h>

// Problem maxima: N=100000, E=1600000, IN=128, H=64
#define MAXN 100000
#define MAXE 1600000
#define HDIM 64

typedef unsigned long long u64;

// ---------------- scratch (static device globals) ----------------------------
__device__ int     g_deg_in[MAXN];
__device__ int     g_deg_out[MAXN];
__device__ int     g_row_start[MAXN + 1];
__device__ int     g_cursor[MAXN];
__device__ int     g_csr_src[MAXE];
__device__ int     g_bsums[128];
__device__ float   g_norm_src[MAXN];
__device__ float   g_norm_dst[MAXN];
// Encoder-interleaved: row (node*2 + enc), 64 fp16 = 128B per row
__device__ __align__(16) __half2 g_bufAh[(size_t)2 * MAXN * (HDIM / 2)];
__device__ __align__(16) __nv_bfloat16 g_bufBh[(size_t)2 * MAXN * HDIM]; // bf16, nsrc-folded
__device__ float   g_wv[HDIM];
__device__ float   g_bsum;
__device__ double  g_loss;

// ---------------- f32x2 helpers (Blackwell packed FMA) ------------------------
__device__ __forceinline__ u64 pack2(float x) {
    u64 r; asm("mov.b64 %0, {%1, %1};" : "=l"(r) : "f"(x)); return r;
}
__device__ __forceinline__ void ffma2(u64& d, u64 a, u64 b) {
    asm("fma.rn.f32x2 %0, %1, %2, %0;" : "+l"(d) : "l"(a), "l"(b));
}
__device__ __forceinline__ float2 unpack2(u64 v) {
    float2 f; asm("mov.b64 {%0, %1}, %2;" : "=f"(f.x), "=f"(f.y) : "l"(v)); return f;
}
__device__ __forceinline__ uint32_t bf2_bits(__nv_bfloat162 v) {
    uint32_t r; memcpy(&r, &v, 4); return r;
}

// ---------------- setup kernels ----------------------------------------------
__global__ void zero_kernel(int n, int E) {
    int i = blockIdx.x * blockDim.x + threadIdx.x;
    if (i < n) { g_deg_in[i] = 0; g_deg_out[i] = 0; g_cursor[i] = 0; }
    if (i == 0) { g_loss = 0.0; g_row_start[n] = E; }
}

__global__ void degree_kernel(const int* __restrict__ src,
                              const int* __restrict__ dst, int E) {
    int i = blockIdx.x * blockDim.x + threadIdx.x;
    if (i < E) {
        atomicAdd(&g_deg_out[src[i]], 1);
        atomicAdd(&g_deg_in[dst[i]], 1);
    }
}

__global__ void norm_kernel(int n) {
    int i = blockIdx.x * blockDim.x + threadIdx.x;
    if (i < n) {
        g_norm_src[i] = rsqrtf((float)max(g_deg_out[i], 1));
        g_norm_dst[i] = rsqrtf((float)max(g_deg_in[i], 1));
    }
}

__global__ __launch_bounds__(256) void scan1_kernel(int n) {
    __shared__ int warp_tot[8];
    int b = blockIdx.x, t = threadIdx.x;
    int base = b * 1024 + t * 4;
    int d0 = (base + 0 < n) ? g_deg_in[base + 0] : 0;
    int d1 = (base + 1 < n) ? g_deg_in[base + 1] : 0;
    int d2 = (base + 2 < n) ? g_deg_in[base + 2] : 0;
    int d3 = (base + 3 < n) ? g_deg_in[base + 3] : 0;
    int tot = d0 + d1 + d2 + d3;
    int lane = t & 31, w = t >> 5;
    int inc = tot;
    #pragma unroll
    for (int off = 1; off < 32; off <<= 1) {
        int u = __shfl_up_sync(0xffffffffu, inc, off);
        if (lane >= off) inc += u;
    }
    if (lane == 31) warp_tot[w] = inc;
    __syncthreads();
    int woff = 0;
    #pragma unroll
    for (int i = 0; i < 8; i++) if (i < w) woff += warp_tot[i];
    int excl = woff + inc - tot;
    if (base + 0 < n) g_row_start[base + 0] = excl;
    if (base + 1 < n) g_row_start[base + 1] = excl + d0;
    if (base + 2 < n) g_row_start[base + 2] = excl + d0 + d1;
    if (base + 3 < n) g_row_start[base + 3] = excl + d0 + d1 + d2;
    if (t == 255) g_bsums[b] = woff + inc;
}

__global__ __launch_bounds__(256) void scan2_kernel(int n) {
    int b = blockIdx.x, t = threadIdx.x;
    int off = 0;
    for (int i = 0; i < b; i++) off += g_bsums[i];
    int base = b * 1024 + t * 4;
    #pragma unroll
    for (int j = 0; j < 4; j++)
        if (base + j < n) g_row_start[base + j] += off;
}

__global__ void scatter_kernel(const int* __restrict__ src,
                               const int* __restrict__ dst, int E) {
    int i = blockIdx.x * blockDim.x + threadIdx.x;
    if (i < E) {
        int d = dst[i];
        int pos = atomicAdd(&g_cursor[d], 1);
        g_csr_src[g_row_start[d] + pos] = src[i];
    }
}

__global__ void wv_kernel(const float* __restrict__ Wm, const float* __restrict__ bm) {
    int k = threadIdx.x;
    if (k < HDIM) {
        float s = 0.f;
        #pragma unroll 8
        for (int j = 0; j < HDIM; j++) s += Wm[k * HDIM + j];
        g_wv[k] = s;
    }
    if (k == 0) {
        float b = 0.f;
        #pragma unroll 8
        for (int j = 0; j < HDIM; j++) b += bm[j];
        g_bsum = b;
    }
}

// ---------------- GEMM layer 1: 128-row tile, 4x8 thread tile, 3 CTAs/SM ------
// gridDim.y = 2 (encoders). out row index = node*2 + enc (fp16).
__global__ __launch_bounds__(256, 3) void gemm1_kernel(
    const float* __restrict__ X, const float* __restrict__ W,
    const int* __restrict__ perm, const float* __restrict__ nsrc,
    __half2* __restrict__ out, int n)
{
    const int K = 128;
    const int XS_STRIDE = K + 8;   // bf16 units (136)
    const int WS_STRIDE = 68;      // fp32 units
    extern __shared__ char smemc[];
    __nv_bfloat16* Xs = reinterpret_cast<__nv_bfloat16*>(smemc);           // 128 x 136 bf16
    float* Ws = reinterpret_cast<float*>(smemc + 128 * XS_STRIDE * 2);     // 128 x 68 fp32

    const int tid  = threadIdx.x;
    const int enc  = blockIdx.y;
    const int row0 = blockIdx.x * 128;

    // stage X: fuse perm-gather + nsrc scale + bf16 convert
    const float4* X4 = reinterpret_cast<const float4*>(X);
    for (int v = tid; v < 128 * 32; v += 256) {
        int r = v >> 5, kv = v & 31;
        int nd = row0 + r;
        float4 val = make_float4(0.f, 0.f, 0.f, 0.f);
        if (nd < n) {
            int g = enc ? __ldg(&perm[nd]) : nd;
            val = __ldg(X4 + (size_t)g * 32 + kv);
            float s = nsrc[nd];
            val.x *= s; val.y *= s; val.z *= s; val.w *= s;
        }
        u64 pk = ((u64)bf2_bits(__floats2bfloat162_rn(val.z, val.w)) << 32)
               | bf2_bits(__floats2bfloat162_rn(val.x, val.y));
        *reinterpret_cast<u64*>(&Xs[r * XS_STRIDE + kv * 4]) = pk;
    }
    const float4* W4 = reinterpret_cast<const float4*>(W);
    for (int v = tid; v < K * 16; v += 256) {
        *reinterpret_cast<float4*>(&Ws[(v >> 4) * WS_STRIDE + (v & 15) * 4]) = __ldg(W4 + v);
    }
    __syncthreads();

    const int tcol = tid & 7;
    const int trow = tid >> 3;
    const int cg = tcol * 8;
    const int rg = trow * 4;

    u64 acc[4][4];
    #pragma unroll
    for (int r = 0; r < 4; r++)
        #pragma unroll
        for (int c = 0; c < 4; c++) acc[r][c] = 0ull;

    #pragma unroll 2
    for (int k0 = 0; k0 < K; k0 += 4) {
        uint2 xb[4];
        #pragma unroll
        for (int r = 0; r < 4; r++)
            xb[r] = *reinterpret_cast<const uint2*>(&Xs[(rg + r) * XS_STRIDE + k0]);
        #pragma unroll
        for (int kk = 0; kk < 4; kk++) {
            const float* wrow = &Ws[(k0 + kk) * WS_STRIDE + cg];
            ulonglong2 wA = *reinterpret_cast<const ulonglong2*>(wrow);
            ulonglong2 wB = *reinterpret_cast<const ulonglong2*>(wrow + 4);
            #pragma unroll
            for (int r = 0; r < 4; r++) {
                uint32_t b = (kk < 2) ? xb[r].x : xb[r].y;
                uint32_t xbits = (kk & 1) ? (b & 0xFFFF0000u) : (b << 16);
                u64 xp = pack2(__uint_as_float(xbits));
                ffma2(acc[r][0], xp, wA.x);
                ffma2(acc[r][1], xp, wA.y);
                ffma2(acc[r][2], xp, wB.x);
                ffma2(acc[r][3], xp, wB.y);
            }
        }
    }

    #pragma unroll
    for (int r = 0; r < 4; r++) {
        int nd = row0 + rg + r;
        if (nd < n) {
            __half2 hv[4];
            #pragma unroll
            for (int c = 0; c < 4; c++) {
                float2 f = unpack2(acc[r][c]);
                hv[c] = __floats2half2_rn(f.x, f.y);
            }
            *reinterpret_cast<uint4*>(&out[((size_t)nd * 2 + enc) * (HDIM / 2) + tcol * 4]) =
                *reinterpret_cast<const uint4*>(hv);
        }
    }
}

// ---------------- GEMM layer 2: 128-row tile, K=64, rows = 2n interleaved -----
__global__ __launch_bounds__(256, 3) void gemm2_kernel(
    const __nv_bfloat16* __restrict__ X, const float* __restrict__ W,
    __half2* __restrict__ out, int nRows)
{
    const int K = 64;
    const int XS_STRIDE = K + 8;   // 72 bf16
    const int WS_STRIDE = 68;
    extern __shared__ char smemc[];
    __nv_bfloat16* Xs = reinterpret_cast<__nv_bfloat16*>(smemc);           // 128 x 72 bf16
    float* Ws = reinterpret_cast<float*>(smemc + 128 * XS_STRIDE * 2);     // 64 x 68 fp32

    const int tid  = threadIdx.x;
    const int row0 = blockIdx.x * 128;

    const uint4* Xg = reinterpret_cast<const uint4*>(X);
    for (int v = tid; v < 128 * 8; v += 256) {
        int r = v >> 3, q = v & 7;
        int nd = row0 + r;
        uint4 val = make_uint4(0u, 0u, 0u, 0u);
        if (nd < nRows) val = __ldg(Xg + (size_t)nd * 8 + q);
        *reinterpret_cast<uint4*>(&Xs[r * XS_STRIDE + q * 8]) = val;
    }
    const float4* W4 = reinterpret_cast<const float4*>(W);
    for (int v = tid; v < K * 16; v += 256) {
        *reinterpret_cast<float4*>(&Ws[(v >> 4) * WS_STRIDE + (v & 15) * 4]) = __ldg(W4 + v);
    }
    __syncthreads();

    const int tcol = tid & 7;
    const int trow = tid >> 3;
    const int cg = tcol * 8;
    const int rg = trow * 4;

    u64 acc[4][4];
    #pragma unroll
    for (int r = 0; r < 4; r++)
        #pragma unroll
        for (int c = 0; c < 4; c++) acc[r][c] = 0ull;

    #pragma unroll 2
    for (int k0 = 0; k0 < K; k0 += 4) {
        uint2 xb[4];
        #pragma unroll
        for (int r = 0; r < 4; r++)
            xb[r] = *reinterpret_cast<const uint2*>(&Xs[(rg + r) * XS_STRIDE + k0]);
        #pragma unroll
        for (int kk = 0; kk < 4; kk++) {
            const float* wrow = &Ws[(k0 + kk) * WS_STRIDE + cg];
            ulonglong2 wA = *reinterpret_cast<const ulonglong2*>(wrow);
            ulonglong2 wB = *reinterpret_cast<const ulonglong2*>(wrow + 4);
            #pragma unroll
            for (int r = 0; r < 4; r++) {
                uint32_t b = (kk < 2) ? xb[r].x : xb[r].y;
                uint32_t xbits = (kk & 1) ? (b & 0xFFFF0000u) : (b << 16);
                u64 xp = pack2(__uint_as_float(xbits));
                ffma2(acc[r][0], xp, wA.x);
                ffma2(acc[r][1], xp, wA.y);
                ffma2(acc[r][2], xp, wB.x);
                ffma2(acc[r][3], xp, wB.y);
            }
        }
    }

    #pragma unroll
    for (int r = 0; r < 4; r++) {
        int nd = row0 + rg + r;
        if (nd < nRows) {
            __half2 hv[4];
            #pragma unroll
            for (int c = 0; c < 4; c++) {
                float2 f = unpack2(acc[r][c]);
                hv[c] = __floats2half2_rn(f.x, f.y);
            }
            *reinterpret_cast<uint4*>(&out[(size_t)nd * (HDIM / 2) + tcol * 4]) =
                *reinterpret_cast<const uint4*>(hv);
        }
    }
}

// ---------------- aggregation core: pair-edge LDG.128 layout ------------------
// Lane decomposition: sub = lane>>4 (edge within pair), enc = (lane>>3)&1,
// quad = lane&7 (16B chunk = 8 cols). Each lane accumulates 8 cols of one
// encoder over its half of the edges; shfl_xor(16) combines at the end.
// After return: lanes 0..15 hold the full sums (lane = enc*8 + quad).
__device__ __forceinline__ void agg_gather_w(
    const uint4* __restrict__ tin4, int* __restrict__ srcs,
    int node, int lane, float2 acc[4])
{
    const int sub  = lane >> 4;
    const int enc  = (lane >> 3) & 1;
    const int quad = lane & 7;
    int s0 = __ldg(&g_row_start[node]);
    int s1 = __ldg(&g_row_start[node + 1]);
    for (int base = s0; base < s1; base += 32) {
        int idx = base + lane;
        srcs[lane] = (idx < s1) ? __ldg(&g_csr_src[idx]) : 0;
        __syncwarp();
        int cnt = min(32, s1 - base);
        for (int j0 = 0; j0 < cnt; j0 += 8) {
            uint4 v[4];
            int jj[4];
            #pragma unroll
            for (int p = 0; p < 4; p++) {
                int j = j0 + p * 2 + sub;
                jj[p] = j;
                int s = srcs[j & 31];
                v[p] = __ldg(tin4 + ((size_t)s * 2 + enc) * 8 + quad);
            }
            #pragma unroll
            for (int p = 0; p < 4; p++) {
                if (jj[p] < cnt) {
                    const __half2* h = reinterpret_cast<const __half2*>(&v[p]);
                    #pragma unroll
                    for (int q = 0; q < 4; q++) {
                        float2 f = __half22float2(h[q]);
                        acc[q].x += f.x; acc[q].y += f.y;
                    }
                }
            }
        }
        __syncwarp();
    }
    #pragma unroll
    for (int q = 0; q < 4; q++) {
        acc[q].x += __shfl_xor_sync(0xffffffffu, acc[q].x, 16);
        acc[q].y += __shfl_xor_sync(0xffffffffu, acc[q].y, 16);
    }
}

// Layer-1 aggregation: writes bf16 rows with norm_src folded in (gemm2 input).
__global__ __launch_bounds__(256) void agg_kernel(
    const __half2* __restrict__ tin, __nv_bfloat16* __restrict__ tout,
    const float* __restrict__ b, int n)
{
    __shared__ int smem_srcs[8][32];
    int node = (blockIdx.x * blockDim.x + threadIdx.x) >> 5;
    int lane = threadIdx.x & 31;
    int wib  = threadIdx.x >> 5;
    if (node >= n) return;

    float2 acc[4] = {{0.f,0.f},{0.f,0.f},{0.f,0.f},{0.f,0.f}};
    agg_gather_w(reinterpret_cast<const uint4*>(tin), smem_srcs[wib], node, lane, acc);

    if (lane < 16) {
        const int enc  = lane >> 3;
        const int quad = lane & 7;
        float ndst = g_norm_dst[node];
        float ns   = g_norm_src[node];
        float4 b0 = *reinterpret_cast<const float4*>(b + quad * 8);
        float4 b1 = *reinterpret_cast<const float4*>(b + quad * 8 + 4);
        __nv_bfloat162 o[4];
        o[0] = __floats2bfloat162_rn(fmaxf(fmaf(acc[0].x, ndst, b0.x), 0.f) * ns,
                                     fmaxf(fmaf(acc[0].y, ndst, b0.y), 0.f) * ns);
        o[1] = __floats2bfloat162_rn(fmaxf(fmaf(acc[1].x, ndst, b0.z), 0.f) * ns,
                                     fmaxf(fmaf(acc[1].y, ndst, b0.w), 0.f) * ns);
        o[2] = __floats2bfloat162_rn(fmaxf(fmaf(acc[2].x, ndst, b1.x), 0.f) * ns,
                                     fmaxf(fmaf(acc[2].y, ndst, b1.y), 0.f) * ns);
        o[3] = __floats2bfloat162_rn(fmaxf(fmaf(acc[3].x, ndst, b1.z), 0.f) * ns,
                                     fmaxf(fmaf(acc[3].y, ndst, b1.w), 0.f) * ns);
        *reinterpret_cast<uint4*>(tout + ((size_t)node * 2 + enc) * HDIM + quad * 8) =
            *reinterpret_cast<const uint4*>(o);
    }
}

// Layer-2 aggregation fused with scoring + loss.
__global__ __launch_bounds__(256) void agg_score_kernel(
    const __half2* __restrict__ tin, const float* __restrict__ b,
    const float* __restrict__ labels, int n)
{
    __shared__ int smem_srcs[8][32];
    __shared__ float sw[8];
    int node = (blockIdx.x * blockDim.x + threadIdx.x) >> 5;
    int lane = threadIdx.x & 31;
    int wib  = threadIdx.x >> 5;

    float term = 0.f;
    if (node < n) {
        float2 acc[4] = {{0.f,0.f},{0.f,0.f},{0.f,0.f},{0.f,0.f}};
        agg_gather_w(reinterpret_cast<const uint4*>(tin), smem_srcs[wib], node, lane, acc);

        const int quad = lane & 7;
        float ndst = g_norm_dst[node];
        float4 b0 = *reinterpret_cast<const float4*>(b + quad * 8);
        float4 b1 = *reinterpret_cast<const float4*>(b + quad * 8 + 4);
        float4 w0 = *reinterpret_cast<const float4*>(&g_wv[quad * 8]);
        float4 w1 = *reinterpret_cast<const float4*>(&g_wv[quad * 8 + 4]);

        float p = fmaxf(fmaf(acc[0].x, ndst, b0.x), 0.f) * w0.x
                + fmaxf(fmaf(acc[0].y, ndst, b0.y), 0.f) * w0.y
                + fmaxf(fmaf(acc[1].x, ndst, b0.z), 0.f) * w0.z
                + fmaxf(fmaf(acc[1].y, ndst, b0.w), 0.f) * w0.w
                + fmaxf(fmaf(acc[2].x, ndst, b1.x), 0.f) * w1.x
                + fmaxf(fmaf(acc[2].y, ndst, b1.y), 0.f) * w1.y
                + fmaxf(fmaf(acc[3].x, ndst, b1.z), 0.f) * w1.z
                + fmaxf(fmaf(acc[3].y, ndst, b1.w), 0.f) * w1.w;
        // reduce over 8-lane groups -> lane 0 (enc0), lane 8 (enc1)
        p += __shfl_down_sync(0xffffffffu, p, 4);
        p += __shfl_down_sync(0xffffffffu, p, 2);
        p += __shfl_down_sync(0xffffffffu, p, 1);
        float p1 = __shfl_sync(0xffffffffu, p, 8);
        if (lane == 0) {
            float sc0 = p + g_bsum;
            float sc1 = p1 + g_bsum;
            float y0 = labels[node];
            float y1 = labels[(size_t)n + node];
            term = fmaxf(sc0, 0.f) + log1pf(expf(-fabsf(sc0))) - sc0 * y0
                 + fmaxf(sc1, 0.f) + log1pf(expf(-fabsf(sc1))) - sc1 * y1;
        }
    }
    if (lane == 0) sw[wib] = term;
    __syncthreads();
    if (threadIdx.x == 0) {
        float s = 0.f;
        #pragma unroll
        for (int w = 0; w < 8; w++) s += sw[w];
        atomicAdd(&g_loss, (double)s);
    }
}

__global__ void finalize_kernel(float* __restrict__ out, double inv) {
    out[0] = (float)(g_loss * inv);
}

// ---------------- launch -----------------------------------------------------
extern "C" void kernel_launch(void* const* d_in, const int* in_sizes, int n_in,
                              void* d_out, int out_size) {
    const float* features = (const float*)d_in[0];
    const float* labels   = (const float*)d_in[1];
    const float* W1 = (const float*)d_in[2];
    const float* b1 = (const float*)d_in[3];
    const float* W2 = (const float*)d_in[4];
    const float* b2 = (const float*)d_in[5];
    const float* Wm = (const float*)d_in[6];
    const float* bm = (const float*)d_in[7];
    const int* src  = (const int*)d_in[8];
    const int* dst  = (const int*)d_in[9];
    const int* perm = (const int*)d_in[10];

    int E = in_sizes[8];
    int n = in_sizes[10];

    __half2* bufA; __nv_bfloat16* bufB; float* nsrc;
    cudaGetSymbolAddress((void**)&bufA, g_bufAh);
    cudaGetSymbolAddress((void**)&bufB, g_bufBh);
    cudaGetSymbolAddress((void**)&nsrc, g_norm_src);

    const int SMEM1 = 128 * 136 * 2 + 128 * 68 * 4;   // 34,816 + 34,816 = 69,632 B
    const int SMEM2 = 128 * 72 * 2 + 64 * 68 * 4;     // 18,432 + 17,408 = 35,840 B
    cudaFuncSetAttribute(gemm1_kernel, cudaFuncAttributeMaxDynamicSharedMemorySize, SMEM1);
    cudaFuncSetAttribute(gemm2_kernel, cudaFuncAttributeMaxDynamicSharedMemorySize, SMEM2);

    int nb256  = (n + 255) / 256;
    int eb256  = (E + 255) / 256;
    int scanB  = (n + 1023) / 1024;
    dim3 gemm1G((n + 127) / 128, 2);
    int  gemm2B = (2 * n + 127) / 128;
    int  warpB  = (n + 7) / 8;

    // gemm1 kept 4th for the fixed-slot ncu capture.
    zero_kernel<<<nb256, 256>>>(n, E);
    degree_kernel<<<eb256, 256>>>(src, dst, E);
    norm_kernel<<<nb256, 256>>>(n);
    gemm1_kernel<<<gemm1G, 256, SMEM1>>>(features, W1, perm, nsrc, bufA, n);
    scan1_kernel<<<scanB, 256>>>(n);
    scan2_kernel<<<scanB, 256>>>(n);
    scatter_kernel<<<eb256, 256>>>(src, dst, E);
    wv_kernel<<<1, 64>>>(Wm, bm);

    agg_kernel<<<warpB, 256>>>(bufA, bufB, b1, n);
    gemm2_kernel<<<gemm2B, 256, SMEM2>>>(bufB, W2, bufA, 2 * n);
    agg_score_kernel<<<warpB, 256>>>(bufA, b2, labels, n);

    finalize_kernel<<<1, 1>>>((float*)d_out, 0.5 / (double)n);
}

// round 11
// speedup vs baseline: 1.1153x; 1.1153x over previous
#include <cuda_runtime.h>
#include <cuda_fp16.h>
#include <cuda_bf16.h>
#include <math.h>
#include <stdint.h>
#include <string.h>

// Problem maxima: N=100000, E=1600000, IN=128, H=64
#define MAXN 100000
#define MAXE 1600000
#define HDIM 64

typedef unsigned long long u64;

// ---------------- scratch (static device globals) ----------------------------
__device__ int     g_deg_in[MAXN];
__device__ int     g_deg_out[MAXN];
__device__ int     g_row_start[MAXN + 1];
__device__ int     g_cursor[MAXN];
__device__ int     g_csr_src[MAXE];
__device__ int     g_bsums[128];
__device__ float   g_norm_src[MAXN];
__device__ float   g_norm_dst[MAXN];
// Encoder-interleaved: row (node*2 + enc)
__device__ __align__(16) __half2 g_bufAh[(size_t)2 * MAXN * (HDIM / 2)];       // gemm out (fp16)
__device__ __align__(16) __nv_bfloat16 g_bufBh[(size_t)2 * MAXN * HDIM];        // agg out (bf16, nsrc-folded)
__device__ float   g_wv[HDIM];
__device__ float   g_bsum;
__device__ double  g_loss;

// ---------------- f32x2 helpers (Blackwell packed FMA) ------------------------
__device__ __forceinline__ u64 pack2(float x) {
    u64 r; asm("mov.b64 %0, {%1, %1};" : "=l"(r) : "f"(x)); return r;
}
__device__ __forceinline__ void ffma2(u64& d, u64 a, u64 b) {
    asm("fma.rn.f32x2 %0, %1, %2, %0;" : "+l"(d) : "l"(a), "l"(b));
}
__device__ __forceinline__ float2 unpack2(u64 v) {
    float2 f; asm("mov.b64 {%0, %1}, %2;" : "=f"(f.x), "=f"(f.y) : "l"(v)); return f;
}
__device__ __forceinline__ uint32_t bf2_bits(__nv_bfloat162 v) {
    uint32_t r; memcpy(&r, &v, 4); return r;
}

// ---------------- setup kernels ----------------------------------------------
__global__ void zero_kernel(int n, int E) {
    int i = blockIdx.x * blockDim.x + threadIdx.x;
    if (i < n) { g_deg_in[i] = 0; g_deg_out[i] = 0; g_cursor[i] = 0; }
    if (i == 0) { g_loss = 0.0; g_row_start[n] = E; }
}

__global__ void degree_kernel(const int* __restrict__ src,
                              const int* __restrict__ dst, int E) {
    int i = blockIdx.x * blockDim.x + threadIdx.x;
    if (i < E) {
        atomicAdd(&g_deg_out[src[i]], 1);
        atomicAdd(&g_deg_in[dst[i]], 1);
    }
}

__global__ void norm_kernel(int n) {
    int i = blockIdx.x * blockDim.x + threadIdx.x;
    if (i < n) {
        g_norm_src[i] = rsqrtf((float)max(g_deg_out[i], 1));
        g_norm_dst[i] = rsqrtf((float)max(g_deg_in[i], 1));
    }
}

__global__ __launch_bounds__(256) void scan1_kernel(int n) {
    __shared__ int warp_tot[8];
    int b = blockIdx.x, t = threadIdx.x;
    int base = b * 1024 + t * 4;
    int d0 = (base + 0 < n) ? g_deg_in[base + 0] : 0;
    int d1 = (base + 1 < n) ? g_deg_in[base + 1] : 0;
    int d2 = (base + 2 < n) ? g_deg_in[base + 2] : 0;
    int d3 = (base + 3 < n) ? g_deg_in[base + 3] : 0;
    int tot = d0 + d1 + d2 + d3;
    int lane = t & 31, w = t >> 5;
    int inc = tot;
    #pragma unroll
    for (int off = 1; off < 32; off <<= 1) {
        int u = __shfl_up_sync(0xffffffffu, inc, off);
        if (lane >= off) inc += u;
    }
    if (lane == 31) warp_tot[w] = inc;
    __syncthreads();
    int woff = 0;
    #pragma unroll
    for (int i = 0; i < 8; i++) if (i < w) woff += warp_tot[i];
    int excl = woff + inc - tot;
    if (base + 0 < n) g_row_start[base + 0] = excl;
    if (base + 1 < n) g_row_start[base + 1] = excl + d0;
    if (base + 2 < n) g_row_start[base + 2] = excl + d0 + d1;
    if (base + 3 < n) g_row_start[base + 3] = excl + d0 + d1 + d2;
    if (t == 255) g_bsums[b] = woff + inc;
}

__global__ __launch_bounds__(256) void scan2_kernel(int n) {
    int b = blockIdx.x, t = threadIdx.x;
    int off = 0;
    for (int i = 0; i < b; i++) off += g_bsums[i];
    int base = b * 1024 + t * 4;
    #pragma unroll
    for (int j = 0; j < 4; j++)
        if (base + j < n) g_row_start[base + j] += off;
}

__global__ void scatter_kernel(const int* __restrict__ src,
                               const int* __restrict__ dst, int E) {
    int i = blockIdx.x * blockDim.x + threadIdx.x;
    if (i < E) {
        int d = dst[i];
        int pos = atomicAdd(&g_cursor[d], 1);
        g_csr_src[g_row_start[d] + pos] = src[i];
    }
}

__global__ void wv_kernel(const float* __restrict__ Wm, const float* __restrict__ bm) {
    int k = threadIdx.x;
    if (k < HDIM) {
        float s = 0.f;
        #pragma unroll 8
        for (int j = 0; j < HDIM; j++) s += Wm[k * HDIM + j];
        g_wv[k] = s;
    }
    if (k == 0) {
        float b = 0.f;
        #pragma unroll 8
        for (int j = 0; j < HDIM; j++) b += bm[j];
        g_bsum = b;
    }
}

// ---------------- GEMM layer 1: 256-row tile, 8x8 thread tile (R8 config) -----
__global__ __launch_bounds__(256, 2) void gemm1_kernel(
    const float* __restrict__ X, const float* __restrict__ W,
    const int* __restrict__ perm, const float* __restrict__ nsrc,
    __half2* __restrict__ out, int n)
{
    const int K = 128;
    const int XS_STRIDE = K + 8;
    const int WS_STRIDE = 68;
    extern __shared__ char smemc[];
    __nv_bfloat16* Xs = reinterpret_cast<__nv_bfloat16*>(smemc);
    float* Ws = reinterpret_cast<float*>(smemc + 256 * XS_STRIDE * 2);

    const int tid  = threadIdx.x;
    const int enc  = blockIdx.y;
    const int row0 = blockIdx.x * 256;

    const float4* X4 = reinterpret_cast<const float4*>(X);
    for (int v = tid; v < 256 * 32; v += 256) {
        int r = v >> 5, kv = v & 31;
        int nd = row0 + r;
        float4 val = make_float4(0.f, 0.f, 0.f, 0.f);
        if (nd < n) {
            int g = enc ? __ldg(&perm[nd]) : nd;
            val = __ldg(X4 + (size_t)g * 32 + kv);
            float s = nsrc[nd];
            val.x *= s; val.y *= s; val.z *= s; val.w *= s;
        }
        u64 pk = ((u64)bf2_bits(__floats2bfloat162_rn(val.z, val.w)) << 32)
               | bf2_bits(__floats2bfloat162_rn(val.x, val.y));
        *reinterpret_cast<u64*>(&Xs[r * XS_STRIDE + kv * 4]) = pk;
    }
    const float4* W4 = reinterpret_cast<const float4*>(W);
    for (int v = tid; v < K * 16; v += 256) {
        *reinterpret_cast<float4*>(&Ws[(v >> 4) * WS_STRIDE + (v & 15) * 4]) = __ldg(W4 + v);
    }
    __syncthreads();

    const int tcol = tid & 7;
    const int trow = tid >> 3;
    const int cg = tcol * 8;
    const int rg = trow * 8;

    u64 acc[8][4];
    #pragma unroll
    for (int r = 0; r < 8; r++)
        #pragma unroll
        for (int c = 0; c < 4; c++) acc[r][c] = 0ull;

    #pragma unroll 2
    for (int k0 = 0; k0 < K; k0 += 4) {
        uint2 xb[8];
        #pragma unroll
        for (int r = 0; r < 8; r++)
            xb[r] = *reinterpret_cast<const uint2*>(&Xs[(rg + r) * XS_STRIDE + k0]);
        #pragma unroll
        for (int kk = 0; kk < 4; kk++) {
            const float* wrow = &Ws[(k0 + kk) * WS_STRIDE + cg];
            ulonglong2 wA = *reinterpret_cast<const ulonglong2*>(wrow);
            ulonglong2 wB = *reinterpret_cast<const ulonglong2*>(wrow + 4);
            #pragma unroll
            for (int r = 0; r < 8; r++) {
                uint32_t b = (kk < 2) ? xb[r].x : xb[r].y;
                uint32_t xbits = (kk & 1) ? (b & 0xFFFF0000u) : (b << 16);
                u64 xp = pack2(__uint_as_float(xbits));
                ffma2(acc[r][0], xp, wA.x);
                ffma2(acc[r][1], xp, wA.y);
                ffma2(acc[r][2], xp, wB.x);
                ffma2(acc[r][3], xp, wB.y);
            }
        }
    }

    #pragma unroll
    for (int r = 0; r < 8; r++) {
        int nd = row0 + rg + r;
        if (nd < n) {
            __half2 hv[4];
            #pragma unroll
            for (int c = 0; c < 4; c++) {
                float2 f = unpack2(acc[r][c]);
                hv[c] = __floats2half2_rn(f.x, f.y);
            }
            *reinterpret_cast<uint4*>(&out[((size_t)nd * 2 + enc) * (HDIM / 2) + tcol * 4]) =
                *reinterpret_cast<const uint4*>(hv);
        }
    }
}

// ---------------- GEMM layer 2: 256-row tile, K=64, rows = 2n interleaved -----
__global__ __launch_bounds__(256, 2) void gemm2_kernel(
    const __nv_bfloat16* __restrict__ X, const float* __restrict__ W,
    __half2* __restrict__ out, int nRows)
{
    const int K = 64;
    const int XS_STRIDE = K + 8;
    const int WS_STRIDE = 68;
    extern __shared__ char smemc[];
    __nv_bfloat16* Xs = reinterpret_cast<__nv_bfloat16*>(smemc);
    float* Ws = reinterpret_cast<float*>(smemc + 256 * XS_STRIDE * 2);

    const int tid  = threadIdx.x;
    const int row0 = blockIdx.x * 256;

    const uint4* Xg = reinterpret_cast<const uint4*>(X);
    for (int v = tid; v < 256 * 8; v += 256) {
        int r = v >> 3, q = v & 7;
        int nd = row0 + r;
        uint4 val = make_uint4(0u, 0u, 0u, 0u);
        if (nd < nRows) val = __ldg(Xg + (size_t)nd * 8 + q);
        *reinterpret_cast<uint4*>(&Xs[r * XS_STRIDE + q * 8]) = val;
    }
    const float4* W4 = reinterpret_cast<const float4*>(W);
    for (int v = tid; v < K * 16; v += 256) {
        *reinterpret_cast<float4*>(&Ws[(v >> 4) * WS_STRIDE + (v & 15) * 4]) = __ldg(W4 + v);
    }
    __syncthreads();

    const int tcol = tid & 7;
    const int trow = tid >> 3;
    const int cg = tcol * 8;
    const int rg = trow * 8;

    u64 acc[8][4];
    #pragma unroll
    for (int r = 0; r < 8; r++)
        #pragma unroll
        for (int c = 0; c < 4; c++) acc[r][c] = 0ull;

    #pragma unroll 2
    for (int k0 = 0; k0 < K; k0 += 4) {
        uint2 xb[8];
        #pragma unroll
        for (int r = 0; r < 8; r++)
            xb[r] = *reinterpret_cast<const uint2*>(&Xs[(rg + r) * XS_STRIDE + k0]);
        #pragma unroll
        for (int kk = 0; kk < 4; kk++) {
            const float* wrow = &Ws[(k0 + kk) * WS_STRIDE + cg];
            ulonglong2 wA = *reinterpret_cast<const ulonglong2*>(wrow);
            ulonglong2 wB = *reinterpret_cast<const ulonglong2*>(wrow + 4);
            #pragma unroll
            for (int r = 0; r < 8; r++) {
                uint32_t b = (kk < 2) ? xb[r].x : xb[r].y;
                uint32_t xbits = (kk & 1) ? (b & 0xFFFF0000u) : (b << 16);
                u64 xp = pack2(__uint_as_float(xbits));
                ffma2(acc[r][0], xp, wA.x);
                ffma2(acc[r][1], xp, wA.y);
                ffma2(acc[r][2], xp, wB.x);
                ffma2(acc[r][3], xp, wB.y);
            }
        }
    }

    #pragma unroll
    for (int r = 0; r < 8; r++) {
        int nd = row0 + rg + r;
        if (nd < nRows) {
            __half2 hv[4];
            #pragma unroll
            for (int c = 0; c < 4; c++) {
                float2 f = unpack2(acc[r][c]);
                hv[c] = __floats2half2_rn(f.x, f.y);
            }
            *reinterpret_cast<uint4*>(&out[(size_t)nd * (HDIM / 2) + tcol * 4]) =
                *reinterpret_cast<const uint4*>(hv);
        }
    }
}

// ---------------- aggregation core (R8 version) -------------------------------
__device__ __forceinline__ void agg_gather2(
    const __half2* __restrict__ tin, int* __restrict__ srcs,
    int node, int lane,
    float& a0x, float& a0y, float& a1x, float& a1y)
{
    int s0 = __ldg(&g_row_start[node]);
    int s1 = __ldg(&g_row_start[node + 1]);
    for (int base = s0; base < s1; base += 32) {
        int idx = base + lane;
        srcs[lane] = (idx < s1) ? __ldg(&g_csr_src[idx]) : 0;
        __syncwarp();
        int cnt = min(32, s1 - base);
        for (int j0 = 0; j0 < cnt; j0 += 8) {
            float2 v0[8], v1[8];
            #pragma unroll
            for (int jj = 0; jj < 8; jj++) {
                int s = srcs[j0 + jj];
                const __half2* p = tin + ((size_t)s * 2) * (HDIM / 2) + lane;
                v0[jj] = __half22float2(__ldg(p));
                v1[jj] = __half22float2(__ldg(p + (HDIM / 2)));
            }
            #pragma unroll
            for (int jj = 0; jj < 8; jj++) {
                if (j0 + jj < cnt) {
                    a0x += v0[jj].x; a0y += v0[jj].y;
                    a1x += v1[jj].x; a1y += v1[jj].y;
                }
            }
        }
        __syncwarp();
    }
}

__global__ __launch_bounds__(256) void agg_kernel(
    const __half2* __restrict__ tin, __nv_bfloat16* __restrict__ tout,
    const float* __restrict__ b, int n)
{
    __shared__ int smem_srcs[8][32];
    int node = (blockIdx.x * blockDim.x + threadIdx.x) >> 5;
    int lane = threadIdx.x & 31;
    int wib  = threadIdx.x >> 5;
    if (node >= n) return;

    float a0x = 0.f, a0y = 0.f, a1x = 0.f, a1y = 0.f;
    agg_gather2(tin, smem_srcs[wib], node, lane, a0x, a0y, a1x, a1y);

    float nd = g_norm_dst[node];
    float ns = g_norm_src[node];
    float2 bb = *reinterpret_cast<const float2*>(b + lane * 2);
    __nv_bfloat162 o0 = __floats2bfloat162_rn(
        fmaxf(fmaf(a0x, nd, bb.x), 0.f) * ns, fmaxf(fmaf(a0y, nd, bb.y), 0.f) * ns);
    __nv_bfloat162 o1 = __floats2bfloat162_rn(
        fmaxf(fmaf(a1x, nd, bb.x), 0.f) * ns, fmaxf(fmaf(a1y, nd, bb.y), 0.f) * ns);
    __nv_bfloat16* r0 = tout + ((size_t)node * 2) * HDIM;
    *reinterpret_cast<__nv_bfloat162*>(r0 + lane * 2) = o0;
    *reinterpret_cast<__nv_bfloat162*>(r0 + HDIM + lane * 2) = o1;
}

__global__ __launch_bounds__(256) void agg_score_kernel(
    const __half2* __restrict__ tin, const float* __restrict__ b,
    const float* __restrict__ labels, int n)
{
    __shared__ int smem_srcs[8][32];
    __shared__ float sw[8];
    int node = (blockIdx.x * blockDim.x + threadIdx.x) >> 5;
    int lane = threadIdx.x & 31;
    int wib  = threadIdx.x >> 5;

    float term = 0.f;
    if (node < n) {
        float a0x = 0.f, a0y = 0.f, a1x = 0.f, a1y = 0.f;
        agg_gather2(tin, smem_srcs[wib], node, lane, a0x, a0y, a1x, a1y);

        float nd = g_norm_dst[node];
        float2 bb = *reinterpret_cast<const float2*>(b + lane * 2);
        float2 wv = *reinterpret_cast<const float2*>(&g_wv[lane * 2]);

        float o0x = fmaxf(fmaf(a0x, nd, bb.x), 0.f);
        float o0y = fmaxf(fmaf(a0y, nd, bb.y), 0.f);
        float o1x = fmaxf(fmaf(a1x, nd, bb.x), 0.f);
        float o1y = fmaxf(fmaf(a1y, nd, bb.y), 0.f);

        float p0 = o0x * wv.x + o0y * wv.y;
        float p1 = o1x * wv.x + o1y * wv.y;
        #pragma unroll
        for (int o = 16; o; o >>= 1) {
            p0 += __shfl_down_sync(0xffffffffu, p0, o);
            p1 += __shfl_down_sync(0xffffffffu, p1, o);
        }
        if (lane == 0) {
            float sc0 = p0 + g_bsum;
            float sc1 = p1 + g_bsum;
            float y0 = labels[node];
            float y1 = labels[(size_t)n + node];
            term = fmaxf(sc0, 0.f) + log1pf(expf(-fabsf(sc0))) - sc0 * y0
                 + fmaxf(sc1, 0.f) + log1pf(expf(-fabsf(sc1))) - sc1 * y1;
        }
    }
    if (lane == 0) sw[wib] = term;
    __syncthreads();
    if (threadIdx.x == 0) {
        float s = 0.f;
        #pragma unroll
        for (int w = 0; w < 8; w++) s += sw[w];
        atomicAdd(&g_loss, (double)s);
    }
}

__global__ void finalize_kernel(float* __restrict__ out, double inv) {
    out[0] = (float)(g_loss * inv);
}

// ---------------- launch -----------------------------------------------------
extern "C" void kernel_launch(void* const* d_in, const int* in_sizes, int n_in,
                              void* d_out, int out_size) {
    const float* features = (const float*)d_in[0];
    const float* labels   = (const float*)d_in[1];
    const float* W1 = (const float*)d_in[2];
    const float* b1 = (const float*)d_in[3];
    const float* W2 = (const float*)d_in[4];
    const float* b2 = (const float*)d_in[5];
    const float* Wm = (const float*)d_in[6];
    const float* bm = (const float*)d_in[7];
    const int* src  = (const int*)d_in[8];
    const int* dst  = (const int*)d_in[9];
    const int* perm = (const int*)d_in[10];

    int E = in_sizes[8];
    int n = in_sizes[10];

    __half2* bufA; __nv_bfloat16* bufB; float* nsrc;
    cudaGetSymbolAddress((void**)&bufA, g_bufAh);
    cudaGetSymbolAddress((void**)&bufB, g_bufBh);
    cudaGetSymbolAddress((void**)&nsrc, g_norm_src);

    const int SMEM1 = 256 * 136 * 2 + 128 * 68 * 4;   // 104,448 B
    const int SMEM2 = 256 * 72 * 2 + 64 * 68 * 4;     //  54,272 B
    cudaFuncSetAttribute(gemm1_kernel, cudaFuncAttributeMaxDynamicSharedMemorySize, SMEM1);
    cudaFuncSetAttribute(gemm2_kernel, cudaFuncAttributeMaxDynamicSharedMemorySize, SMEM2);

    // One-time side stream + events (host-side resources, created on first
    // call; per-call captured work is identical every call).
    static cudaStream_t s_side = nullptr;
    static cudaEvent_t ev_fork = nullptr, ev_join = nullptr;
    if (!s_side) {
        cudaStreamCreateWithFlags(&s_side, cudaStreamNonBlocking);
        cudaEventCreateWithFlags(&ev_fork, cudaEventDisableTiming);
        cudaEventCreateWithFlags(&ev_join, cudaEventDisableTiming);
    }

    int nb256  = (n + 255) / 256;
    int eb256  = (E + 255) / 256;
    int scanB  = (n + 1023) / 1024;
    dim3 gemm1G((n + 255) / 256, 2);
    int  gemm2B = (2 * n + 255) / 256;
    int  warpB  = (n + 7) / 8;

    zero_kernel<<<nb256, 256>>>(n, E);
    degree_kernel<<<eb256, 256>>>(src, dst, E);
    norm_kernel<<<nb256, 256>>>(n);

    // Fork BEFORE gemm1: CSR build (depends only on degree) overlaps gemm1.
    cudaEventRecord(ev_fork, 0);
    cudaStreamWaitEvent(s_side, ev_fork, 0);

    gemm1_kernel<<<gemm1G, 256, SMEM1>>>(features, W1, perm, nsrc, bufA, n); // 4th kernel (ncu slot)

    scan1_kernel<<<scanB, 256, 0, s_side>>>(n);
    scan2_kernel<<<scanB, 256, 0, s_side>>>(n);
    scatter_kernel<<<eb256, 256, 0, s_side>>>(src, dst, E);
    wv_kernel<<<1, 64, 0, s_side>>>(Wm, bm);
    cudaEventRecord(ev_join, s_side);
    cudaStreamWaitEvent(0, ev_join, 0);

    agg_kernel<<<warpB, 256>>>(bufA, bufB, b1, n);
    gemm2_kernel<<<gemm2B, 256, SMEM2>>>(bufB, W2, bufA, 2 * n);
    agg_score_kernel<<<warpB, 256>>>(bufA, b2, labels, n);

    finalize_kernel<<<1, 1>>>((float*)d_out, 0.5 / (double)n);
}

// round 12
// speedup vs baseline: 1.4140x; 1.2679x over previous
#include <cuda_runtime.h>
#include <cuda_fp16.h>
#include <cuda_bf16.h>
#include <math.h>
#include <stdint.h>
#include <string.h>

// Problem maxima: N=100000, E=1600000, IN=128, H=64
#define MAXN 100000
#define MAXE 1600000
#define HDIM 64

typedef unsigned long long u64;

// ---------------- scratch (static device globals) ----------------------------
__device__ int     g_deg_in[MAXN];
__device__ int     g_deg_out[MAXN];
__device__ int     g_row_start[MAXN + 1];
__device__ int     g_cursor[MAXN];
__device__ int     g_csr_src[MAXE];
__device__ int     g_bsums[128];
__device__ int     g_iperm[MAXN];
__device__ float   g_norm_src[MAXN];
__device__ float   g_norm_dst[MAXN];
// Encoder-interleaved: row (node*2 + enc)
__device__ __align__(16) __half2 g_bufAh[(size_t)2 * MAXN * (HDIM / 2)];       // gemm out (fp16)
__device__ __align__(16) __nv_bfloat16 g_bufBh[(size_t)2 * MAXN * HDIM];        // agg out (bf16, nsrc-folded)
__device__ float   g_wv[HDIM];
__device__ float   g_bsum;
__device__ double  g_loss;

// ---------------- f32x2 helpers (Blackwell packed FMA) ------------------------
__device__ __forceinline__ u64 pack2(float x) {
    u64 r; asm("mov.b64 %0, {%1, %1};" : "=l"(r) : "f"(x)); return r;
}
__device__ __forceinline__ void ffma2(u64& d, u64 a, u64 b) {
    asm("fma.rn.f32x2 %0, %1, %2, %0;" : "+l"(d) : "l"(a), "l"(b));
}
__device__ __forceinline__ float2 unpack2(u64 v) {
    float2 f; asm("mov.b64 {%0, %1}, %2;" : "=f"(f.x), "=f"(f.y) : "l"(v)); return f;
}
__device__ __forceinline__ uint32_t bf2_bits(__nv_bfloat162 v) {
    uint32_t r; memcpy(&r, &v, 4); return r;
}

// ---------------- setup kernels ----------------------------------------------
__global__ void zero_kernel(int n, int E) {
    int i = blockIdx.x * blockDim.x + threadIdx.x;
    if (i < n) { g_deg_in[i] = 0; g_deg_out[i] = 0; g_cursor[i] = 0; }
    if (i == 0) { g_loss = 0.0; g_row_start[n] = E; }
}

__global__ void degree_kernel(const int* __restrict__ src,
                              const int* __restrict__ dst, int E) {
    int i = blockIdx.x * blockDim.x + threadIdx.x;
    if (i < E) {
        atomicAdd(&g_deg_out[src[i]], 1);
        atomicAdd(&g_deg_in[dst[i]], 1);
    }
}

// Also builds the inverse permutation used by gemm1's dual-write epilogue.
__global__ void norm_kernel(const int* __restrict__ perm, int n) {
    int i = blockIdx.x * blockDim.x + threadIdx.x;
    if (i < n) {
        g_norm_src[i] = rsqrtf((float)max(g_deg_out[i], 1));
        g_norm_dst[i] = rsqrtf((float)max(g_deg_in[i], 1));
        g_iperm[__ldg(&perm[i])] = i;
    }
}

__global__ __launch_bounds__(256) void scan1_kernel(int n) {
    __shared__ int warp_tot[8];
    int b = blockIdx.x, t = threadIdx.x;
    int base = b * 1024 + t * 4;
    int d0 = (base + 0 < n) ? g_deg_in[base + 0] : 0;
    int d1 = (base + 1 < n) ? g_deg_in[base + 1] : 0;
    int d2 = (base + 2 < n) ? g_deg_in[base + 2] : 0;
    int d3 = (base + 3 < n) ? g_deg_in[base + 3] : 0;
    int tot = d0 + d1 + d2 + d3;
    int lane = t & 31, w = t >> 5;
    int inc = tot;
    #pragma unroll
    for (int off = 1; off < 32; off <<= 1) {
        int u = __shfl_up_sync(0xffffffffu, inc, off);
        if (lane >= off) inc += u;
    }
    if (lane == 31) warp_tot[w] = inc;
    __syncthreads();
    int woff = 0;
    #pragma unroll
    for (int i = 0; i < 8; i++) if (i < w) woff += warp_tot[i];
    int excl = woff + inc - tot;
    if (base + 0 < n) g_row_start[base + 0] = excl;
    if (base + 1 < n) g_row_start[base + 1] = excl + d0;
    if (base + 2 < n) g_row_start[base + 2] = excl + d0 + d1;
    if (base + 3 < n) g_row_start[base + 3] = excl + d0 + d1 + d2;
    if (t == 255) g_bsums[b] = woff + inc;
}

__global__ __launch_bounds__(256) void scan2_kernel(int n) {
    int b = blockIdx.x, t = threadIdx.x;
    int off = 0;
    for (int i = 0; i < b; i++) off += g_bsums[i];
    int base = b * 1024 + t * 4;
    #pragma unroll
    for (int j = 0; j < 4; j++)
        if (base + j < n) g_row_start[base + j] += off;
}

__global__ void scatter_kernel(const int* __restrict__ src,
                               const int* __restrict__ dst, int E) {
    int i = blockIdx.x * blockDim.x + threadIdx.x;
    if (i < E) {
        int d = dst[i];
        int pos = atomicAdd(&g_cursor[d], 1);
        g_csr_src[g_row_start[d] + pos] = src[i];
    }
}

__global__ void wv_kernel(const float* __restrict__ Wm, const float* __restrict__ bm) {
    int k = threadIdx.x;
    if (k < HDIM) {
        float s = 0.f;
        #pragma unroll 8
        for (int j = 0; j < HDIM; j++) s += Wm[k * HDIM + j];
        g_wv[k] = s;
    }
    if (k == 0) {
        float b = 0.f;
        #pragma unroll 8
        for (int j = 0; j < HDIM; j++) b += bm[j];
        g_bsum = b;
    }
}

// ---------------- GEMM layer 1: Y = X @ W1 computed ONCE ----------------------
// 256-row tile, 8x8 thread tile. Epilogue writes each Y row twice:
//   enc0: norm[r]        * Y[r] -> out row (r*2 + 0)
//   enc1: norm[iperm[r]] * Y[r] -> out row (iperm[r]*2 + 1)
__global__ __launch_bounds__(256, 2) void gemm1_kernel(
    const float* __restrict__ X, const float* __restrict__ W,
    const float* __restrict__ nsrc, __half2* __restrict__ out, int n)
{
    const int K = 128;
    const int XS_STRIDE = K + 8;
    const int WS_STRIDE = 68;
    extern __shared__ char smemc[];
    __nv_bfloat16* Xs = reinterpret_cast<__nv_bfloat16*>(smemc);
    float* Ws = reinterpret_cast<float*>(smemc + 256 * XS_STRIDE * 2);

    const int tid  = threadIdx.x;
    const int row0 = blockIdx.x * 256;

    // stage X (unscaled, no gather) as bf16
    const float4* X4 = reinterpret_cast<const float4*>(X);
    for (int v = tid; v < 256 * 32; v += 256) {
        int r = v >> 5, kv = v & 31;
        int nd = row0 + r;
        float4 val = make_float4(0.f, 0.f, 0.f, 0.f);
        if (nd < n) val = __ldg(X4 + (size_t)nd * 32 + kv);
        u64 pk = ((u64)bf2_bits(__floats2bfloat162_rn(val.z, val.w)) << 32)
               | bf2_bits(__floats2bfloat162_rn(val.x, val.y));
        *reinterpret_cast<u64*>(&Xs[r * XS_STRIDE + kv * 4]) = pk;
    }
    const float4* W4 = reinterpret_cast<const float4*>(W);
    for (int v = tid; v < K * 16; v += 256) {
        *reinterpret_cast<float4*>(&Ws[(v >> 4) * WS_STRIDE + (v & 15) * 4]) = __ldg(W4 + v);
    }
    __syncthreads();

    const int tcol = tid & 7;
    const int trow = tid >> 3;
    const int cg = tcol * 8;
    const int rg = trow * 8;

    u64 acc[8][4];
    #pragma unroll
    for (int r = 0; r < 8; r++)
        #pragma unroll
        for (int c = 0; c < 4; c++) acc[r][c] = 0ull;

    #pragma unroll 2
    for (int k0 = 0; k0 < K; k0 += 4) {
        uint2 xb[8];
        #pragma unroll
        for (int r = 0; r < 8; r++)
            xb[r] = *reinterpret_cast<const uint2*>(&Xs[(rg + r) * XS_STRIDE + k0]);
        #pragma unroll
        for (int kk = 0; kk < 4; kk++) {
            const float* wrow = &Ws[(k0 + kk) * WS_STRIDE + cg];
            ulonglong2 wA = *reinterpret_cast<const ulonglong2*>(wrow);
            ulonglong2 wB = *reinterpret_cast<const ulonglong2*>(wrow + 4);
            #pragma unroll
            for (int r = 0; r < 8; r++) {
                uint32_t b = (kk < 2) ? xb[r].x : xb[r].y;
                uint32_t xbits = (kk & 1) ? (b & 0xFFFF0000u) : (b << 16);
                u64 xp = pack2(__uint_as_float(xbits));
                ffma2(acc[r][0], xp, wA.x);
                ffma2(acc[r][1], xp, wA.y);
                ffma2(acc[r][2], xp, wB.x);
                ffma2(acc[r][3], xp, wB.y);
            }
        }
    }

    #pragma unroll
    for (int r = 0; r < 8; r++) {
        int nd = row0 + rg + r;
        if (nd < n) {
            float2 f[4];
            #pragma unroll
            for (int c = 0; c < 4; c++) f[c] = unpack2(acc[r][c]);

            // enc0: scale by norm[nd], row (nd*2)
            float s0 = __ldg(&nsrc[nd]);
            __half2 h0[4];
            #pragma unroll
            for (int c = 0; c < 4; c++)
                h0[c] = __floats2half2_rn(f[c].x * s0, f[c].y * s0);
            *reinterpret_cast<uint4*>(&out[((size_t)nd * 2) * (HDIM / 2) + tcol * 4]) =
                *reinterpret_cast<const uint4*>(h0);

            // enc1: scale by norm[iperm[nd]], row (iperm[nd]*2 + 1)
            int i2 = __ldg(&g_iperm[nd]);
            float s1 = __ldg(&nsrc[i2]);
            __half2 h1[4];
            #pragma unroll
            for (int c = 0; c < 4; c++)
                h1[c] = __floats2half2_rn(f[c].x * s1, f[c].y * s1);
            *reinterpret_cast<uint4*>(&out[((size_t)i2 * 2 + 1) * (HDIM / 2) + tcol * 4]) =
                *reinterpret_cast<const uint4*>(h1);
        }
    }
}

// ---------------- GEMM layer 2: 256-row tile, K=64, rows = 2n interleaved -----
__global__ __launch_bounds__(256, 2) void gemm2_kernel(
    const __nv_bfloat16* __restrict__ X, const float* __restrict__ W,
    __half2* __restrict__ out, int nRows)
{
    const int K = 64;
    const int XS_STRIDE = K + 8;
    const int WS_STRIDE = 68;
    extern __shared__ char smemc[];
    __nv_bfloat16* Xs = reinterpret_cast<__nv_bfloat16*>(smemc);
    float* Ws = reinterpret_cast<float*>(smemc + 256 * XS_STRIDE * 2);

    const int tid  = threadIdx.x;
    const int row0 = blockIdx.x * 256;

    const uint4* Xg = reinterpret_cast<const uint4*>(X);
    for (int v = tid; v < 256 * 8; v += 256) {
        int r = v >> 3, q = v & 7;
        int nd = row0 + r;
        uint4 val = make_uint4(0u, 0u, 0u, 0u);
        if (nd < nRows) val = __ldg(Xg + (size_t)nd * 8 + q);
        *reinterpret_cast<uint4*>(&Xs[r * XS_STRIDE + q * 8]) = val;
    }
    const float4* W4 = reinterpret_cast<const float4*>(W);
    for (int v = tid; v < K * 16; v += 256) {
        *reinterpret_cast<float4*>(&Ws[(v >> 4) * WS_STRIDE + (v & 15) * 4]) = __ldg(W4 + v);
    }
    __syncthreads();

    const int tcol = tid & 7;
    const int trow = tid >> 3;
    const int cg = tcol * 8;
    const int rg = trow * 8;

    u64 acc[8][4];
    #pragma unroll
    for (int r = 0; r < 8; r++)
        #pragma unroll
        for (int c = 0; c < 4; c++) acc[r][c] = 0ull;

    #pragma unroll 2
    for (int k0 = 0; k0 < K; k0 += 4) {
        uint2 xb[8];
        #pragma unroll
        for (int r = 0; r < 8; r++)
            xb[r] = *reinterpret_cast<const uint2*>(&Xs[(rg + r) * XS_STRIDE + k0]);
        #pragma unroll
        for (int kk = 0; kk < 4; kk++) {
            const float* wrow = &Ws[(k0 + kk) * WS_STRIDE + cg];
            ulonglong2 wA = *reinterpret_cast<const ulonglong2*>(wrow);
            ulonglong2 wB = *reinterpret_cast<const ulonglong2*>(wrow + 4);
            #pragma unroll
            for (int r = 0; r < 8; r++) {
                uint32_t b = (kk < 2) ? xb[r].x : xb[r].y;
                uint32_t xbits = (kk & 1) ? (b & 0xFFFF0000u) : (b << 16);
                u64 xp = pack2(__uint_as_float(xbits));
                ffma2(acc[r][0], xp, wA.x);
                ffma2(acc[r][1], xp, wA.y);
                ffma2(acc[r][2], xp, wB.x);
                ffma2(acc[r][3], xp, wB.y);
            }
        }
    }

    #pragma unroll
    for (int r = 0; r < 8; r++) {
        int nd = row0 + rg + r;
        if (nd < nRows) {
            __half2 hv[4];
            #pragma unroll
            for (int c = 0; c < 4; c++) {
                float2 f = unpack2(acc[r][c]);
                hv[c] = __floats2half2_rn(f.x, f.y);
            }
            *reinterpret_cast<uint4*>(&out[(size_t)nd * (HDIM / 2) + tcol * 4]) =
                *reinterpret_cast<const uint4*>(hv);
        }
    }
}

// ---------------- aggregation core ------------------------------------------
__device__ __forceinline__ void agg_gather2(
    const __half2* __restrict__ tin, int* __restrict__ srcs,
    int node, int lane,
    float& a0x, float& a0y, float& a1x, float& a1y)
{
    int s0 = __ldg(&g_row_start[node]);
    int s1 = __ldg(&g_row_start[node + 1]);
    for (int base = s0; base < s1; base += 32) {
        int idx = base + lane;
        srcs[lane] = (idx < s1) ? __ldg(&g_csr_src[idx]) : 0;
        __syncwarp();
        int cnt = min(32, s1 - base);
        for (int j0 = 0; j0 < cnt; j0 += 8) {
            float2 v0[8], v1[8];
            #pragma unroll
            for (int jj = 0; jj < 8; jj++) {
                int s = srcs[j0 + jj];
                const __half2* p = tin + ((size_t)s * 2) * (HDIM / 2) + lane;
                v0[jj] = __half22float2(__ldg(p));
                v1[jj] = __half22float2(__ldg(p + (HDIM / 2)));
            }
            #pragma unroll
            for (int jj = 0; jj < 8; jj++) {
                if (j0 + jj < cnt) {
                    a0x += v0[jj].x; a0y += v0[jj].y;
                    a1x += v1[jj].x; a1y += v1[jj].y;
                }
            }
        }
        __syncwarp();
    }
}

__global__ __launch_bounds__(256) void agg_kernel(
    const __half2* __restrict__ tin, __nv_bfloat16* __restrict__ tout,
    const float* __restrict__ b, int n)
{
    __shared__ int smem_srcs[8][32];
    int node = (blockIdx.x * blockDim.x + threadIdx.x) >> 5;
    int lane = threadIdx.x & 31;
    int wib  = threadIdx.x >> 5;
    if (node >= n) return;

    float a0x = 0.f, a0y = 0.f, a1x = 0.f, a1y = 0.f;
    agg_gather2(tin, smem_srcs[wib], node, lane, a0x, a0y, a1x, a1y);

    float nd = g_norm_dst[node];
    float ns = g_norm_src[node];
    float2 bb = *reinterpret_cast<const float2*>(b + lane * 2);
    __nv_bfloat162 o0 = __floats2bfloat162_rn(
        fmaxf(fmaf(a0x, nd, bb.x), 0.f) * ns, fmaxf(fmaf(a0y, nd, bb.y), 0.f) * ns);
    __nv_bfloat162 o1 = __floats2bfloat162_rn(
        fmaxf(fmaf(a1x, nd, bb.x), 0.f) * ns, fmaxf(fmaf(a1y, nd, bb.y), 0.f) * ns);
    __nv_bfloat16* r0 = tout + ((size_t)node * 2) * HDIM;
    *reinterpret_cast<__nv_bfloat162*>(r0 + lane * 2) = o0;
    *reinterpret_cast<__nv_bfloat162*>(r0 + HDIM + lane * 2) = o1;
}

__global__ __launch_bounds__(256) void agg_score_kernel(
    const __half2* __restrict__ tin, const float* __restrict__ b,
    const float* __restrict__ labels, int n)
{
    __shared__ int smem_srcs[8][32];
    __shared__ float sw[8];
    int node = (blockIdx.x * blockDim.x + threadIdx.x) >> 5;
    int lane = threadIdx.x & 31;
    int wib  = threadIdx.x >> 5;

    float term = 0.f;
    if (node < n) {
        float a0x = 0.f, a0y = 0.f, a1x = 0.f, a1y = 0.f;
        agg_gather2(tin, smem_srcs[wib], node, lane, a0x, a0y, a1x, a1y);

        float nd = g_norm_dst[node];
        float2 bb = *reinterpret_cast<const float2*>(b + lane * 2);
        float2 wv = *reinterpret_cast<const float2*>(&g_wv[lane * 2]);

        float o0x = fmaxf(fmaf(a0x, nd, bb.x), 0.f);
        float o0y = fmaxf(fmaf(a0y, nd, bb.y), 0.f);
        float o1x = fmaxf(fmaf(a1x, nd, bb.x), 0.f);
        float o1y = fmaxf(fmaf(a1y, nd, bb.y), 0.f);

        float p0 = o0x * wv.x + o0y * wv.y;
        float p1 = o1x * wv.x + o1y * wv.y;
        #pragma unroll
        for (int o = 16; o; o >>= 1) {
            p0 += __shfl_down_sync(0xffffffffu, p0, o);
            p1 += __shfl_down_sync(0xffffffffu, p1, o);
        }
        if (lane == 0) {
            float sc0 = p0 + g_bsum;
            float sc1 = p1 + g_bsum;
            float y0 = labels[node];
            float y1 = labels[(size_t)n + node];
            term = fmaxf(sc0, 0.f) + log1pf(expf(-fabsf(sc0))) - sc0 * y0
                 + fmaxf(sc1, 0.f) + log1pf(expf(-fabsf(sc1))) - sc1 * y1;
        }
    }
    if (lane == 0) sw[wib] = term;
    __syncthreads();
    if (threadIdx.x == 0) {
        float s = 0.f;
        #pragma unroll
        for (int w = 0; w < 8; w++) s += sw[w];
        atomicAdd(&g_loss, (double)s);
    }
}

__global__ void finalize_kernel(float* __restrict__ out, double inv) {
    out[0] = (float)(g_loss * inv);
}

// ---------------- launch -----------------------------------------------------
extern "C" void kernel_launch(void* const* d_in, const int* in_sizes, int n_in,
                              void* d_out, int out_size) {
    const float* features = (const float*)d_in[0];
    const float* labels   = (const float*)d_in[1];
    const float* W1 = (const float*)d_in[2];
    const float* b1 = (const float*)d_in[3];
    const float* W2 = (const float*)d_in[4];
    const float* b2 = (const float*)d_in[5];
    const float* Wm = (const float*)d_in[6];
    const float* bm = (const float*)d_in[7];
    const int* src  = (const int*)d_in[8];
    const int* dst  = (const int*)d_in[9];
    const int* perm = (const int*)d_in[10];

    int E = in_sizes[8];
    int n = in_sizes[10];

    __half2* bufA; __nv_bfloat16* bufB; float* nsrc;
    cudaGetSymbolAddress((void**)&bufA, g_bufAh);
    cudaGetSymbolAddress((void**)&bufB, g_bufBh);
    cudaGetSymbolAddress((void**)&nsrc, g_norm_src);

    const int SMEM1 = 256 * 136 * 2 + 128 * 68 * 4;   // 104,448 B
    const int SMEM2 = 256 * 72 * 2 + 64 * 68 * 4;     //  54,272 B
    cudaFuncSetAttribute(gemm1_kernel, cudaFuncAttributeMaxDynamicSharedMemorySize, SMEM1);
    cudaFuncSetAttribute(gemm2_kernel, cudaFuncAttributeMaxDynamicSharedMemorySize, SMEM2);

    // One-time side stream + events (host-side resources).
    static cudaStream_t s_side = nullptr;
    static cudaEvent_t ev_fork = nullptr, ev_join = nullptr;
    if (!s_side) {
        cudaStreamCreateWithFlags(&s_side, cudaStreamNonBlocking);
        cudaEventCreateWithFlags(&ev_fork, cudaEventDisableTiming);
        cudaEventCreateWithFlags(&ev_join, cudaEventDisableTiming);
    }

    int nb256  = (n + 255) / 256;
    int eb256  = (E + 255) / 256;
    int scanB  = (n + 1023) / 1024;
    int gemm1B = (n + 255) / 256;          // single pass now
    int gemm2B = (2 * n + 255) / 256;
    int warpB  = (n + 7) / 8;

    zero_kernel<<<nb256, 256>>>(n, E);
    degree_kernel<<<eb256, 256>>>(src, dst, E);
    norm_kernel<<<nb256, 256>>>(perm, n);

    // Fork BEFORE gemm1: CSR build overlaps gemm1.
    cudaEventRecord(ev_fork, 0);
    cudaStreamWaitEvent(s_side, ev_fork, 0);

    gemm1_kernel<<<gemm1B, 256, SMEM1>>>(features, W1, nsrc, bufA, n); // 4th kernel (ncu slot)

    scan1_kernel<<<scanB, 256, 0, s_side>>>(n);
    scan2_kernel<<<scanB, 256, 0, s_side>>>(n);
    scatter_kernel<<<eb256, 256, 0, s_side>>>(src, dst, E);
    wv_kernel<<<1, 64, 0, s_side>>>(Wm, bm);
    cudaEventRecord(ev_join, s_side);
    cudaStreamWaitEvent(0, ev_join, 0);

    agg_kernel<<<warpB, 256>>>(bufA, bufB, b1, n);
    gemm2_kernel<<<gemm2B, 256, SMEM2>>>(bufB, W2, bufA, 2 * n);
    agg_score_kernel<<<warpB, 256>>>(bufA, b2, labels, n);

    finalize_kernel<<<1, 1>>>((float*)d_out, 0.5 / (double)n);
}